// round 13
// baseline (speedup 1.0000x reference)
#include <cuda_runtime.h>
#include <cuda_fp16.h>
#include <cstdint>

#define BB 4
#define CC 64
#define FD 50000
#define KN 16
#define BN_EPS 1e-5f

#define GEMM_TILES 391      // (FD+127)/128
#define GTILES 782          // (FD+63)/64
#define NORM_CHUNKS 6250    // FD/8
#define GEMM_CTAS (BB * GEMM_TILES)
#define GATHER_CTAS (BB * GTILES)
#define NORM_CTAS (BB * CC * NORM_CHUNKS / 256)   // 6250
#define TOTAL_CTAS (GEMM_CTAS + GATHER_CTAS + NORM_CTAS)

__device__ __half g_buf[BB * FD * CC];   // g[b][f][o] fp16
__device__ __half g_yt[BB * CC * FD];    // y_t[b][c][f] fp16
__device__ float g_sum[CC];
__device__ float g_sq[CC];
__device__ int g_done[BB];
__device__ int g_gdone;
__device__ int g_npass;

// ---------------------------------------------------------------------------
__device__ __forceinline__ uint32_t smem_u32(const void* p) {
    uint32_t a;
    asm("{ .reg .u64 t; cvta.to.shared.u64 t, %1; cvt.u32.u64 %0, t; }"
        : "=r"(a) : "l"(p));
    return a;
}
__device__ __forceinline__ int ld_acquire_gpu(const int* p) {
    int v;
    asm volatile("ld.acquire.gpu.b32 %0, [%1];" : "=r"(v) : "l"(p) : "memory");
    return v;
}
__device__ __forceinline__ void ldsm_x4(uint32_t& r0, uint32_t& r1,
                                        uint32_t& r2, uint32_t& r3, uint32_t addr) {
    asm volatile("ldmatrix.sync.aligned.m8n8.x4.shared.b16 {%0,%1,%2,%3}, [%4];"
                 : "=r"(r0), "=r"(r1), "=r"(r2), "=r"(r3) : "r"(addr));
}
__device__ __forceinline__ void ldsm_x4_trans(uint32_t& r0, uint32_t& r1,
                                              uint32_t& r2, uint32_t& r3, uint32_t addr) {
    asm volatile("ldmatrix.sync.aligned.m8n8.x4.trans.shared.b16 {%0,%1,%2,%3}, [%4];"
                 : "=r"(r0), "=r"(r1), "=r"(r2), "=r"(r3) : "r"(addr));
}
__device__ __forceinline__ void mma16816(float* c, uint32_t a0, uint32_t a1,
                                         uint32_t a2, uint32_t a3,
                                         uint32_t b0, uint32_t b1) {
    asm volatile(
        "mma.sync.aligned.m16n8k16.row.col.f32.f16.f16.f32 "
        "{%0,%1,%2,%3}, {%4,%5,%6,%7}, {%8,%9}, {%0,%1,%2,%3};"
        : "+f"(c[0]), "+f"(c[1]), "+f"(c[2]), "+f"(c[3])
        : "r"(a0), "r"(a1), "r"(a2), "r"(a3), "r"(b0), "r"(b1));
}

// ---------------------------------------------------------------------------
#define SPA 136  // sA row stride halves (272B == 16 mod 128)
#define SPB 72   // sB row stride halves (144B == 16 mod 128)

struct SmemGemm {
    __align__(16) __half A[64 * SPA];
    __align__(16) __half B[64 * SPB];
};
struct SmemGather {
    float tile[64][65];     // y fp32, pad 65 (read rows 2l: stride 130 -> 2-way, OK)
    float ssum[CC];
    float ssq[CC];
};
union SmemU { SmemGemm g; SmemGather h; };

// ---------------------------------------------------------------------------
// Mega-kernel: [gemm CTAs][gather CTAs][norm CTAs] in dispatch order.
__global__ __launch_bounds__(256)
void mega_kernel(const float* __restrict__ fea, const float* __restrict__ W,
                 const int* __restrict__ ring, const float* __restrict__ bias,
                 const float* __restrict__ gamma, const float* __restrict__ beta,
                 float* __restrict__ out) {
    __shared__ SmemU sm;
    const int bid = blockIdx.x;
    const int t = threadIdx.x;
    const int wid = t >> 5, lane = t & 31;

    if (bid < GEMM_CTAS) {
        // =================== phase A: GEMM ===================
        const int b = bid / GEMM_TILES;
        const int tile = bid % GEMM_TILES;
        const int f0 = tile * 128;
        __half* sA = sm.g.A;
        __half* sB = sm.g.B;

        // stage B = W [64o][64c] fp16
        {
            const int o = t >> 2, q = t & 3;
            union { __half2 h2[8]; uint4 u[2]; } pk;
#pragma unroll
            for (int i = 0; i < 4; i++) {
                float4 wv = *(const float4*)(W + o * CC + q * 16 + 4 * i);
                pk.h2[2 * i]     = __floats2half2_rn(wv.x, wv.y);
                pk.h2[2 * i + 1] = __floats2half2_rn(wv.z, wv.w);
            }
            uint4* dst = (uint4*)(sB + o * SPB + q * 16);
            dst[0] = pk.u[0];
            dst[1] = pk.u[1];
        }
        // stage A = fea tile [64c][128f] fp16
        const float* feab = fea + (size_t)b * (CC * FD);
        const int nv = min(128, FD - f0);
        {
            const int c = t >> 2, q = t & 3;
            const float* src = feab + c * FD + f0 + q * 32;
            __half* dstrow = sA + c * SPA + q * 32;
#pragma unroll
            for (int i = 0; i < 8; i++) {
                float4 v = make_float4(0.f, 0.f, 0.f, 0.f);
                if (q * 32 + 4 * i + 3 < nv) v = *(const float4*)(src + 4 * i);
                union { __half2 h2[2]; unsigned long long u; } pk;
                pk.h2[0] = __floats2half2_rn(v.x, v.y);
                pk.h2[1] = __floats2half2_rn(v.z, v.w);
                *(unsigned long long*)(dstrow + 4 * i) = pk.u;
            }
        }
        __syncthreads();

        const uint32_t aBase = smem_u32(sA);
        const uint32_t bBase = smem_u32(sB);
        const int m0 = wid * 16;
        const int g = lane >> 3, r = lane & 7;
        const uint32_t aKoff = (g >> 1) * 8 + r;
        const uint32_t aMcol = m0 + (g & 1) * 8;
        const uint32_t bRowOff = (lane >> 4) * 8 + (lane & 7);
        const uint32_t bColOff = ((lane >> 3) & 1) * 8;

        float acc[8][4];
#pragma unroll
        for (int j = 0; j < 8; j++)
#pragma unroll
            for (int m = 0; m < 4; m++) acc[j][m] = 0.f;

#pragma unroll
        for (int kk = 0; kk < 4; kk++) {
            uint32_t a0, a1, a2, a3;
            ldsm_x4_trans(a0, a1, a2, a3,
                          aBase + ((kk * 16 + aKoff) * SPA + aMcol) * 2);
#pragma unroll
            for (int j = 0; j < 4; j++) {
                uint32_t b0, b1, b2, b3;
                ldsm_x4(b0, b1, b2, b3,
                        bBase + ((16 * j + bRowOff) * SPB + kk * 16 + bColOff) * 2);
                mma16816(acc[2 * j],     a0, a1, a2, a3, b0, b1);
                mma16816(acc[2 * j + 1], a0, a1, a2, a3, b2, b3);
            }
        }

        const int fr = f0 + m0 + (lane >> 2);
        const int colq = 2 * (lane & 3);
        __half* gb = g_buf + (size_t)b * (FD * CC);
        if (fr < FD) {
            __half* row = gb + (size_t)fr * CC;
#pragma unroll
            for (int j = 0; j < 8; j++)
                *(__half2*)(row + 8 * j + colq) = __floats2half2_rn(acc[j][0], acc[j][1]);
        }
        if (fr + 8 < FD) {
            __half* row = gb + (size_t)(fr + 8) * CC;
#pragma unroll
            for (int j = 0; j < 8; j++)
                *(__half2*)(row + 8 * j + colq) = __floats2half2_rn(acc[j][2], acc[j][3]);
        }

        __syncthreads();
        __threadfence();
        if (t == 0) atomicAdd(&g_done[b], 1);

    } else if (bid < GEMM_CTAS + GATHER_CTAS) {
        // =================== phase B: GATHER + transpose ===================
        const int gid = bid - GEMM_CTAS;
        const int b = gid / GTILES;
        const int f0 = (gid % GTILES) * 64;

        // prefetch ring indices (8 faces per warp) before the spin
        int myidx[8];
#pragma unroll
        for (int i = 0; i < 8; i++) {
            int f = f0 + wid * 8 + i;
            myidx[i] = 0;
            if (f < FD && lane < KN) {
                int v = ring[((long long)(b * FD + f)) * KN + lane];
                if ((unsigned)v < (unsigned)FD) myidx[i] = v;
            }
        }
        if (t < CC) { sm.h.ssum[t] = 0.f; sm.h.ssq[t] = 0.f; }

        if (t == 0) {
            while (ld_acquire_gpu(&g_done[b]) < GEMM_TILES) __nanosleep(200);
        }
        __syncthreads();

        const __half2* gb = (const __half2*)(g_buf + (size_t)b * (FD * CC));
        const float bias0 = bias[2 * lane];
        const float bias1 = bias[2 * lane + 1];
        float s0 = 0.f, s1 = 0.f, q0 = 0.f, q1 = 0.f;

#pragma unroll
        for (int i = 0; i < 8; i++) {
            int f = f0 + wid * 8 + i;
            if (f >= FD) continue;
            float accx = 0.f, accy = 0.f;
#pragma unroll
            for (int k = 0; k < KN; k++) {
                int idx = __shfl_sync(0xffffffffu, myidx[i], k);
                float2 v = __half22float2(gb[(size_t)idx * 32 + lane]);
                accx += v.x;
                accy += v.y;
            }
            float y0 = accx + bias0;
            float y1 = accy + bias1;
            sm.h.tile[wid * 8 + i][2 * lane]     = y0;
            sm.h.tile[wid * 8 + i][2 * lane + 1] = y1;
            s0 += y0; q0 += y0 * y0;
            s1 += y1; q1 += y1 * y1;
        }

        atomicAdd(&sm.h.ssum[2 * lane],     s0);
        atomicAdd(&sm.h.ssum[2 * lane + 1], s1);
        atomicAdd(&sm.h.ssq[2 * lane],      q0);
        atomicAdd(&sm.h.ssq[2 * lane + 1],  q1);
        __syncthreads();

        // transposed write: y_t[b][c][f0 + 2*lane .. +1] fp16 (coalesced 128B rows)
        {
            const int ff = f0 + 2 * lane;
            if (ff + 1 < FD) {
                for (int c = wid; c < CC; c += 8) {
                    __half2 hv = __floats2half2_rn(sm.h.tile[2 * lane][c],
                                                   sm.h.tile[2 * lane + 1][c]);
                    *(__half2*)(g_yt + ((size_t)(b * CC + c)) * FD + ff) = hv;
                }
            }
        }

        if (t < CC) {
            atomicAdd(&g_sum[t], sm.h.ssum[t]);
            atomicAdd(&g_sq[t],  sm.h.ssq[t]);
        }
        __syncthreads();
        __threadfence();
        if (t == 0) atomicAdd(&g_gdone, 1);

    } else {
        // =================== phase C: NORM (streaming) ===================
        const int nid = bid - GEMM_CTAS - GATHER_CTAS;

        if (t == 0) {
            while (ld_acquire_gpu(&g_gdone) < GATHER_CTAS) __nanosleep(500);
        }
        __syncthreads();

        const int id = nid * 256 + t;              // chunk of 8 faces
        const int b = id / (CC * NORM_CHUNKS);
        const int rem = id % (CC * NORM_CHUNKS);
        const int c = rem / NORM_CHUNKS;
        const int f0 = (rem % NORM_CHUNKS) * 8;

        const float inv_n = 1.0f / (float)(BB * FD);
        const float mean = g_sum[c] * inv_n;
        const float var  = g_sq[c] * inv_n - mean * mean;
        const float sc = gamma[c] * rsqrtf(var + BN_EPS);
        const float sh = beta[c] - mean * sc;

        const size_t base = ((size_t)(b * CC + c)) * FD + f0;
        uint4 v = *(const uint4*)(g_yt + base);
        const __half2* hp = (const __half2*)&v;
        float4 o0, o1;
        float2 p;
        p = __half22float2(hp[0]);
        o0.x = fmaxf(fmaf(p.x, sc, sh), 0.f); o0.y = fmaxf(fmaf(p.y, sc, sh), 0.f);
        p = __half22float2(hp[1]);
        o0.z = fmaxf(fmaf(p.x, sc, sh), 0.f); o0.w = fmaxf(fmaf(p.y, sc, sh), 0.f);
        p = __half22float2(hp[2]);
        o1.x = fmaxf(fmaf(p.x, sc, sh), 0.f); o1.y = fmaxf(fmaf(p.y, sc, sh), 0.f);
        p = __half22float2(hp[3]);
        o1.z = fmaxf(fmaf(p.x, sc, sh), 0.f); o1.w = fmaxf(fmaf(p.y, sc, sh), 0.f);
        ((float4*)(out + base))[0] = o0;
        ((float4*)(out + base))[1] = o1;

        // last norm CTA resets all counters/stats for the next graph replay
        __syncthreads();
        if (t == 0) {
            int done = atomicAdd(&g_npass, 1);
            if (done == NORM_CTAS - 1) {
                for (int i = 0; i < BB; i++) g_done[i] = 0;
                g_gdone = 0;
                g_npass = 0;
                for (int i = 0; i < CC; i++) { g_sum[i] = 0.f; g_sq[i] = 0.f; }
            }
        }
    }
}

// ---------------------------------------------------------------------------
extern "C" void kernel_launch(void* const* d_in, const int* in_sizes, int n_in,
                              void* d_out, int out_size) {
    const float* fea   = (const float*)d_in[0];      // [B, C_in, F]
    const int*   ring  = (const int*)d_in[1];        // [B, F, K] int32
    const float* W     = (const float*)d_in[2];      // [C_out, C_in]
    const float* bias  = (const float*)d_in[3];      // [C_out]
    const float* gamma = (const float*)d_in[4];      // [C_out]
    const float* beta  = (const float*)d_in[5];      // [C_out]
    float*       out   = (float*)d_out;              // [B, C_out, F]

    mega_kernel<<<TOTAL_CTAS, 256>>>(fea, W, ring, bias, gamma, beta, out);
}